// round 14
// baseline (speedup 1.0000x reference)
#include <cuda_runtime.h>
#include <math.h>
#include <stdint.h>

#define TT 2048
#define DM 768
#define NH 12
#define HD 64

// Scratch (no cudaMalloc allowed)
__device__ float g_q[TT * DM];
__device__ float g_k[TT * DM];
__device__ float g_v[TT * DM];
__device__ float g_o[TT * DM];

// ---------------------------------------------------------------------------
// TF32 helpers
// ---------------------------------------------------------------------------
__device__ __forceinline__ uint32_t f2tf(float f) {
    uint32_t u;
    asm("cvt.rna.tf32.f32 %0, %1;" : "=r"(u) : "f"(f));
    return u;
}

__device__ __forceinline__ void mma_tf32(float* c, const uint32_t* a, const uint32_t* b) {
    asm volatile(
        "mma.sync.aligned.m16n8k8.row.col.f32.tf32.tf32.f32 "
        "{%0,%1,%2,%3}, {%4,%5,%6,%7}, {%8,%9}, {%0,%1,%2,%3};\n"
        : "+f"(c[0]), "+f"(c[1]), "+f"(c[2]), "+f"(c[3])
        : "r"(a[0]), "r"(a[1]), "r"(a[2]), "r"(a[3]), "r"(b[0]), "r"(b[1]));
}

// ---------------------------------------------------------------------------
// TF32 tensor-core GEMM (NT) — unchanged from r12 (proven).
// Block tile 128x64, BK=32, 256 threads, paired-column smem layout.
// ---------------------------------------------------------------------------
#define RS 40   // row stride in words (32 data + 8 pad)

__device__ __forceinline__ void gemm_tf32_body(
    const float* __restrict__ A, const float* __restrict__ B,
    float* __restrict__ C, const float* __restrict__ vi, float lb,
    int k_begin, int k_end)
{
    __shared__ __align__(16) uint32_t As[128][RS];
    __shared__ __align__(16) uint32_t Bs[64][RS];

    const int bm = blockIdx.y, bn = blockIdx.x;
    const int tid = threadIdx.x;
    const int warp = tid >> 5, lane = tid & 31;
    const int gid = lane >> 2, tig = lane & 3;
    const int wm = warp >> 1, wn = warp & 1;

    const int arow = tid >> 1, acol = (tid & 1) << 4;
    const int brow = tid >> 2, bcol = (tid & 3) << 3;

    const float* Ap = A + (bm * 128 + arow) * DM + acol;
    const float* Bp = B + (bn * 64 + brow) * DM + bcol;

    float c[2][4][4] = {};

    float4 rA[4], rB[2];
    rA[0] = *(const float4*)(Ap + k_begin);
    rA[1] = *(const float4*)(Ap + k_begin + 4);
    rA[2] = *(const float4*)(Ap + k_begin + 8);
    rA[3] = *(const float4*)(Ap + k_begin + 12);
    rB[0] = *(const float4*)(Bp + k_begin);
    rB[1] = *(const float4*)(Bp + k_begin + 4);

    for (int k0 = k_begin; k0 < k_end; k0 += 32) {
        __syncthreads();
        {
            const float* g0 = (const float*)&rA[0];
            const float* g1 = (const float*)&rA[2];
            #pragma unroll
            for (int w = 0; w < 4; w++) {
                *(uint2*)&As[arow][acol + 2 * w] =
                    make_uint2(f2tf(g0[w]), f2tf(g0[w + 4]));
                *(uint2*)&As[arow][acol + 8 + 2 * w] =
                    make_uint2(f2tf(g1[w]), f2tf(g1[w + 4]));
            }
            const float* gb = (const float*)&rB[0];
            #pragma unroll
            for (int w = 0; w < 4; w++) {
                *(uint2*)&Bs[brow][bcol + 2 * w] =
                    make_uint2(f2tf(gb[w]), f2tf(gb[w + 4]));
            }
        }
        __syncthreads();

        if (k0 + 32 < k_end) {
            rA[0] = *(const float4*)(Ap + k0 + 32);
            rA[1] = *(const float4*)(Ap + k0 + 36);
            rA[2] = *(const float4*)(Ap + k0 + 40);
            rA[3] = *(const float4*)(Ap + k0 + 44);
            rB[0] = *(const float4*)(Bp + k0 + 32);
            rB[1] = *(const float4*)(Bp + k0 + 36);
        }

        #pragma unroll
        for (int ks = 0; ks < 32; ks += 8) {
            uint32_t af[2][4], bf[4][2];
            #pragma unroll
            for (int i = 0; i < 2; i++) {
                const int m0 = wm * 32 + i * 16;
                uint2 lo = *(const uint2*)&As[m0 + gid][ks + 2 * tig];
                uint2 hi = *(const uint2*)&As[m0 + 8 + gid][ks + 2 * tig];
                af[i][0] = lo.x; af[i][1] = hi.x;
                af[i][2] = lo.y; af[i][3] = hi.y;
            }
            #pragma unroll
            for (int j = 0; j < 4; j++) {
                const int n0 = wn * 32 + j * 8;
                uint2 bb = *(const uint2*)&Bs[n0 + gid][ks + 2 * tig];
                bf[j][0] = bb.x; bf[j][1] = bb.y;
            }
            #pragma unroll
            for (int i = 0; i < 2; i++)
                #pragma unroll
                for (int j = 0; j < 4; j++)
                    mma_tf32(c[i][j], af[i], bf[j]);
        }
    }

    const float oml = 1.0f - lb;
    #pragma unroll
    for (int i = 0; i < 2; i++) {
        #pragma unroll
        for (int j = 0; j < 4; j++) {
            const int r0 = bm * 128 + wm * 32 + i * 16 + gid;
            const int cn = bn * 64 + wn * 32 + j * 8 + (tig << 1);
            float2 p0 = make_float2(c[i][j][0], c[i][j][1]);
            float2 p1 = make_float2(c[i][j][2], c[i][j][3]);
            if (vi) {
                float2 v0 = *(const float2*)(vi + r0 * DM + cn);
                float2 v1 = *(const float2*)(vi + (r0 + 8) * DM + cn);
                p0.x = oml * p0.x + lb * v0.x;
                p0.y = oml * p0.y + lb * v0.y;
                p1.x = oml * p1.x + lb * v1.x;
                p1.y = oml * p1.y + lb * v1.y;
            }
            *(float2*)(C + r0 * DM + cn) = p0;
            *(float2*)(C + (r0 + 8) * DM + cn) = p1;
        }
    }
}

__global__ __launch_bounds__(256, 2) void gemm_qkv(
    const float* __restrict__ x,
    const float* __restrict__ Wq, const float* __restrict__ Wk,
    const float* __restrict__ Wv,
    const float* __restrict__ vi, const float* __restrict__ lambp,
    float* __restrict__ q, float* __restrict__ k, float* __restrict__ v)
{
    const int z = blockIdx.z;
    const float* B = (z == 0) ? Wq : (z == 1) ? Wk : Wv;
    float* C = (z == 0) ? q : (z == 1) ? k : v;
    const float* mix = (z == 2) ? vi : nullptr;
    const float lb = (z == 2) ? *lambp : 0.0f;
    gemm_tf32_body(x, B, C, mix, lb, 0, DM);
}

__global__ __launch_bounds__(256, 2) void gemm_proj_splitk(
    const float* __restrict__ A, const float* __restrict__ B,
    float* __restrict__ p0, float* __restrict__ p1)
{
    const int z = blockIdx.z;
    gemm_tf32_body(A, B, z ? p1 : p0, nullptr, 0.0f,
                   z ? (DM / 2) : 0, z ? DM : (DM / 2));
}

__global__ __launch_bounds__(256) void add_kernel(
    const float* __restrict__ a, const float* __restrict__ b,
    float* __restrict__ c)
{
    const int i = (blockIdx.x * 256 + threadIdx.x) * 4;
    float4 x = *(const float4*)(a + i);
    float4 y = *(const float4*)(b + i);
    *(float4*)(c + i) = make_float4(x.x + y.x, x.y + y.y, x.z + y.z, x.w + y.w);
}

// ---------------------------------------------------------------------------
// Per-head RMSNorm + RoPE for q and k. grid = T, block = (32, 12).
// ---------------------------------------------------------------------------
__global__ void rmsrope_kernel()
{
    const int t = blockIdx.x;
    const int h = threadIdx.y;
    const int lane = threadIdx.x;

    const float inv = powf(10000.0f, -(float)lane * (1.0f / 32.0f));
    const float ang = (float)t * inv;
    float sn, cs;
    sincosf(ang, &sn, &cs);

    #pragma unroll
    for (int which = 0; which < 2; which++) {
        float* p = (which ? g_k : g_q) + t * DM + h * HD;
        float a = p[lane];
        float b = p[lane + 32];
        float ss = a * a + b * b;
        #pragma unroll
        for (int o = 16; o; o >>= 1)
            ss += __shfl_xor_sync(0xffffffffu, ss, o);
        const float r = rsqrtf(ss * (1.0f / 64.0f) + 1.1920929e-07f);
        a *= r; b *= r;
        p[lane]      =  a * cs + b * sn;
        p[lane + 32] =  b * cs - a * sn;
    }
}

// ---------------------------------------------------------------------------
// Causal flash attention, TF32 tensor cores — v2:
//   * Q fragments hoisted to registers (loaded once from paired smem)
//   * Ks in paired-column layout -> B-fragments via LDS.64
//   * P aliases the Q staging buffer  -> smem 68KB, 2 CTAs/SM
// grid = (T/128, NH) reversed, 256 threads = 8 warps; warp owns 16 q-rows.
// ---------------------------------------------------------------------------
#define AP 68
#define SMEM_ATTN ((64 * AP + 64 * AP + 128 * AP) * 4)

__global__ __launch_bounds__(256, 2) void attn_kernel()
{
    extern __shared__ __align__(16) uint32_t smu[];
    uint32_t (*Ks)[AP] = (uint32_t(*)[AP])(smu);             // paired cols
    uint32_t (*Vs)[AP] = (uint32_t(*)[AP])(smu + 64 * AP);   // plain
    uint32_t (*QP)[AP] = (uint32_t(*)[AP])(smu + 128 * AP);  // Q staging, then P

    const int qb = (int)gridDim.x - 1 - (int)blockIdx.x;   // tall blocks first
    const int h  = blockIdx.y;
    const int tid = threadIdx.x;
    const int wm = tid >> 5;
    const int lane = tid & 31;
    const int gid = lane >> 2, tig = lane & 3;
    const float scale = 0.125f;

    // Stage Q tile (pre-scaled, tf32) in PAIRED layout: within each 8-group,
    // words are (c,c+4),(c+1,c+5),(c+2,c+6),(c+3,c+7).
    {
        const int lr = tid >> 1, lc = (tid & 1) << 5;   // 32 cols = 4 groups
        const float* qp = g_q + (qb * 128 + lr) * DM + h * HD + lc;
        #pragma unroll
        for (int g = 0; g < 4; g++) {
            float4 v0 = *(const float4*)(qp + g * 8);
            float4 v1 = *(const float4*)(qp + g * 8 + 4);
            const float* e0 = (const float*)&v0;
            const float* e1 = (const float*)&v1;
            #pragma unroll
            for (int w = 0; w < 4; w++) {
                *(uint2*)&QP[lr][lc + g * 8 + 2 * w] =
                    make_uint2(f2tf(e0[w] * scale), f2tf(e1[w] * scale));
            }
        }
    }
    __syncthreads();

    // Hoist Q fragments into registers (loop-invariant).
    uint32_t qf[8][4];
    #pragma unroll
    for (int ksi = 0; ksi < 8; ksi++) {
        uint2 lo = *(const uint2*)&QP[wm * 16 + gid][ksi * 8 + 2 * tig];
        uint2 hi = *(const uint2*)&QP[wm * 16 + 8 + gid][ksi * 8 + 2 * tig];
        qf[ksi][0] = lo.x; qf[ksi][1] = hi.x;
        qf[ksi][2] = lo.y; qf[ksi][3] = hi.y;
    }

    float o[8][4] = {};
    float m0 = -1e30f, m1 = -1e30f, l0 = 0.0f, l1 = 0.0f;

    const int r0g = qb * 128 + wm * 16 + gid;
    const int nkb = 2 * qb + 2;

    for (int kb = 0; kb < nkb; kb++) {
        // load K (paired) / V (plain): 4 threads per row, 16 cols each
        {
            const int lr = tid >> 2, lc = (tid & 3) << 4;
            const float* kp = g_k + (kb * 64 + lr) * DM + h * HD + lc;
            const float* vp = g_v + (kb * 64 + lr) * DM + h * HD + lc;
            float4 kv[4], vv[4];
            #pragma unroll
            for (int u = 0; u < 4; u++) {
                kv[u] = *(const float4*)(kp + u * 4);
                vv[u] = *(const float4*)(vp + u * 4);
            }
            __syncthreads();   // prev tile consumed; (kb=0: Q frags loaded)
            const float* k0 = (const float*)&kv[0];   // cols lc+0..7
            const float* k1 = (const float*)&kv[2];   // cols lc+8..15
            #pragma unroll
            for (int w = 0; w < 4; w++) {
                *(uint2*)&Ks[lr][lc + 2 * w] =
                    make_uint2(f2tf(k0[w]), f2tf(k0[w + 4]));
                *(uint2*)&Ks[lr][lc + 8 + 2 * w] =
                    make_uint2(f2tf(k1[w]), f2tf(k1[w + 4]));
            }
            #pragma unroll
            for (int u = 0; u < 4; u++) {
                Vs[lr][lc + u * 4 + 0] = f2tf(vv[u].x);
                Vs[lr][lc + u * 4 + 1] = f2tf(vv[u].y);
                Vs[lr][lc + u * 4 + 2] = f2tf(vv[u].z);
                Vs[lr][lc + u * 4 + 3] = f2tf(vv[u].w);
            }
            __syncthreads();
        }

        const bool act = (qb * 128 + wm * 16 + 15) >= kb * 64;
        if (act) {
            // S = Q @ K^T
            float s[8][4] = {};
            #pragma unroll
            for (int ks = 0; ks < 64; ks += 8) {
                #pragma unroll
                for (int j = 0; j < 8; j++) {
                    uint2 bb = *(const uint2*)&Ks[j * 8 + gid][ks + 2 * tig];
                    uint32_t b[2] = {bb.x, bb.y};
                    mma_tf32(s[j], qf[ks >> 3], b);
                }
            }

            if (kb >= 2 * qb) {
                #pragma unroll
                for (int j = 0; j < 8; j++) {
                    const int c0 = kb * 64 + j * 8 + (tig << 1);
                    if (c0 > r0g)         s[j][0] = -1e30f;
                    if (c0 + 1 > r0g)     s[j][1] = -1e30f;
                    if (c0 > r0g + 8)     s[j][2] = -1e30f;
                    if (c0 + 1 > r0g + 8) s[j][3] = -1e30f;
                }
            }

            float mx0 = -1e30f, mx1 = -1e30f;
            #pragma unroll
            for (int j = 0; j < 8; j++) {
                mx0 = fmaxf(mx0, fmaxf(s[j][0], s[j][1]));
                mx1 = fmaxf(mx1, fmaxf(s[j][2], s[j][3]));
            }
            #pragma unroll
            for (int off = 1; off <= 2; off <<= 1) {
                mx0 = fmaxf(mx0, __shfl_xor_sync(0xffffffffu, mx0, off));
                mx1 = fmaxf(mx1, __shfl_xor_sync(0xffffffffu, mx1, off));
            }
            const float nm0 = fmaxf(m0, mx0), nm1 = fmaxf(m1, mx1);
            const float al0 = __expf(m0 - nm0), al1 = __expf(m1 - nm1);
            float rs0 = 0.0f, rs1 = 0.0f;
            #pragma unroll
            for (int j = 0; j < 8; j++) {
                s[j][0] = __expf(s[j][0] - nm0);
                s[j][1] = __expf(s[j][1] - nm0);
                s[j][2] = __expf(s[j][2] - nm1);
                s[j][3] = __expf(s[j][3] - nm1);
                rs0 += s[j][0] + s[j][1];
                rs1 += s[j][2] + s[j][3];
            }
            #pragma unroll
            for (int off = 1; off <= 2; off <<= 1) {
                rs0 += __shfl_xor_sync(0xffffffffu, rs0, off);
                rs1 += __shfl_xor_sync(0xffffffffu, rs1, off);
            }
            l0 = l0 * al0 + rs0; m0 = nm0;
            l1 = l1 * al1 + rs1; m1 = nm1;
            #pragma unroll
            for (int j = 0; j < 8; j++) {
                o[j][0] *= al0; o[j][1] *= al0;
                o[j][2] *= al1; o[j][3] *= al1;
            }

            // store P (plain layout) into QP (Q staging is dead after hoist)
            #pragma unroll
            for (int j = 0; j < 8; j++) {
                const int c = j * 8 + (tig << 1);
                uint2 p0 = make_uint2(f2tf(s[j][0]), f2tf(s[j][1]));
                uint2 p1 = make_uint2(f2tf(s[j][2]), f2tf(s[j][3]));
                *(uint2*)&QP[wm * 16 + gid][c] = p0;
                *(uint2*)&QP[wm * 16 + 8 + gid][c] = p1;
            }

            // O += P @ V   (self-produced P, V synced above)
            #pragma unroll
            for (int ks = 0; ks < 64; ks += 8) {
                uint32_t a[4];
                a[0] = QP[wm * 16 + gid][ks + tig];
                a[1] = QP[wm * 16 + 8 + gid][ks + tig];
                a[2] = QP[wm * 16 + gid][ks + tig + 4];
                a[3] = QP[wm * 16 + 8 + gid][ks + tig + 4];
                #pragma unroll
                for (int j = 0; j < 8; j++) {
                    uint32_t b[2];
                    b[0] = Vs[ks + tig][j * 8 + gid];
                    b[1] = Vs[ks + tig + 4][j * 8 + gid];
                    mma_tf32(o[j], a, b);
                }
            }
        }
    }

    const float inv0 = 1.0f / l0, inv1 = 1.0f / l1;
    #pragma unroll
    for (int j = 0; j < 8; j++) {
        const int c = h * HD + j * 8 + (tig << 1);
        const int r = qb * 128 + wm * 16 + gid;
        *(float2*)(g_o + r * DM + c) = make_float2(o[j][0] * inv0, o[j][1] * inv0);
        *(float2*)(g_o + (r + 8) * DM + c) = make_float2(o[j][2] * inv1, o[j][3] * inv1);
    }
}

// ---------------------------------------------------------------------------
extern "C" void kernel_launch(void* const* d_in, const int* in_sizes, int n_in,
                              void* d_out, int out_size)
{
    const float* x    = (const float*)d_in[0];
    const float* vi   = (const float*)d_in[1];
    const float* Wq   = (const float*)d_in[2];
    const float* Wk   = (const float*)d_in[3];
    const float* Wv   = (const float*)d_in[4];
    const float* Wp   = (const float*)d_in[5];
    const float* lamb = (const float*)d_in[6];
    float* out = (float*)d_out;

    float *q, *k, *v, *o;
    cudaGetSymbolAddress((void**)&q, g_q);
    cudaGetSymbolAddress((void**)&k, g_k);
    cudaGetSymbolAddress((void**)&v, g_v);
    cudaGetSymbolAddress((void**)&o, g_o);

    cudaFuncSetAttribute(attn_kernel,
                         cudaFuncAttributeMaxDynamicSharedMemorySize, SMEM_ATTN);

    gemm_qkv<<<dim3(DM / 64, TT / 128, 3), 256>>>(x, Wq, Wk, Wv, vi, lamb, q, k, v);
    rmsrope_kernel<<<TT, dim3(32, 12)>>>();
    attn_kernel<<<dim3(TT / 128, NH), 256, SMEM_ATTN>>>();
    // proj with split-K=2: partials into q (now free) and k scratch, then add
    gemm_proj_splitk<<<dim3(DM / 64, TT / 128, 2), 256>>>(o, Wp, q, k);
    add_kernel<<<(TT * DM) / (256 * 4), 256>>>(q, k, out);
}

// round 17
// speedup vs baseline: 1.4523x; 1.4523x over previous
#include <cuda_runtime.h>
#include <math.h>
#include <stdint.h>

#define TT 2048
#define DM 768
#define NH 12
#define HD 64

// Scratch (no cudaMalloc allowed)
__device__ float g_q[TT * DM];
__device__ float g_k[TT * DM];
__device__ float g_v[TT * DM];
__device__ float g_o[TT * DM];
// split-KV partials: up to 4 pieces per row
__device__ float  g_pacc[4 * TT * DM];
__device__ float2 g_ml[4 * NH * TT];

// Work-item table: 40 (qb, piece) pairs per head, longest-first (LPT).
// piece p covers k-tiles [8p, min(8p+8, 2*qb+2)).
__constant__ unsigned char c_qb[40] = {
    3,4,5,6,7,7,8,8,9,9,10,10,11,11,11,12,12,12,13,13,13,14,14,14,15,15,15,15,
    2,6,10,14,  1,5,9,13,  0,4,8,12};
__constant__ unsigned char c_pc[40] = {
    0,0,0,0,0,1,0,1,0,1,0,1,0,1,2,0,1,2,0,1,2,0,1,2,0,1,2,3,
    0,1,2,3,  0,1,2,3,  0,1,2,3};

// ---------------------------------------------------------------------------
// TF32 helpers
// ---------------------------------------------------------------------------
__device__ __forceinline__ uint32_t f2tf(float f) {
    uint32_t u;
    asm("cvt.rna.tf32.f32 %0, %1;" : "=r"(u) : "f"(f));
    return u;
}

__device__ __forceinline__ void mma_tf32(float* c, const uint32_t* a, const uint32_t* b) {
    asm volatile(
        "mma.sync.aligned.m16n8k8.row.col.f32.tf32.tf32.f32 "
        "{%0,%1,%2,%3}, {%4,%5,%6,%7}, {%8,%9}, {%0,%1,%2,%3};\n"
        : "+f"(c[0]), "+f"(c[1]), "+f"(c[2]), "+f"(c[3])
        : "r"(a[0]), "r"(a[1]), "r"(a[2]), "r"(a[3]), "r"(b[0]), "r"(b[1]));
}

// ---------------------------------------------------------------------------
// TF32 tensor-core GEMM (NT) — unchanged from r12 (proven).
// ---------------------------------------------------------------------------
#define RS 40

__device__ __forceinline__ void gemm_tf32_body(
    const float* __restrict__ A, const float* __restrict__ B,
    float* __restrict__ C, const float* __restrict__ vi, float lb,
    int k_begin, int k_end)
{
    __shared__ __align__(16) uint32_t As[128][RS];
    __shared__ __align__(16) uint32_t Bs[64][RS];

    const int bm = blockIdx.y, bn = blockIdx.x;
    const int tid = threadIdx.x;
    const int warp = tid >> 5, lane = tid & 31;
    const int gid = lane >> 2, tig = lane & 3;
    const int wm = warp >> 1, wn = warp & 1;

    const int arow = tid >> 1, acol = (tid & 1) << 4;
    const int brow = tid >> 2, bcol = (tid & 3) << 3;

    const float* Ap = A + (bm * 128 + arow) * DM + acol;
    const float* Bp = B + (bn * 64 + brow) * DM + bcol;

    float c[2][4][4] = {};

    float4 rA[4], rB[2];
    rA[0] = *(const float4*)(Ap + k_begin);
    rA[1] = *(const float4*)(Ap + k_begin + 4);
    rA[2] = *(const float4*)(Ap + k_begin + 8);
    rA[3] = *(const float4*)(Ap + k_begin + 12);
    rB[0] = *(const float4*)(Bp + k_begin);
    rB[1] = *(const float4*)(Bp + k_begin + 4);

    for (int k0 = k_begin; k0 < k_end; k0 += 32) {
        __syncthreads();
        {
            const float* g0 = (const float*)&rA[0];
            const float* g1 = (const float*)&rA[2];
            #pragma unroll
            for (int w = 0; w < 4; w++) {
                *(uint2*)&As[arow][acol + 2 * w] =
                    make_uint2(f2tf(g0[w]), f2tf(g0[w + 4]));
                *(uint2*)&As[arow][acol + 8 + 2 * w] =
                    make_uint2(f2tf(g1[w]), f2tf(g1[w + 4]));
            }
            const float* gb = (const float*)&rB[0];
            #pragma unroll
            for (int w = 0; w < 4; w++) {
                *(uint2*)&Bs[brow][bcol + 2 * w] =
                    make_uint2(f2tf(gb[w]), f2tf(gb[w + 4]));
            }
        }
        __syncthreads();

        if (k0 + 32 < k_end) {
            rA[0] = *(const float4*)(Ap + k0 + 32);
            rA[1] = *(const float4*)(Ap + k0 + 36);
            rA[2] = *(const float4*)(Ap + k0 + 40);
            rA[3] = *(const float4*)(Ap + k0 + 44);
            rB[0] = *(const float4*)(Bp + k0 + 32);
            rB[1] = *(const float4*)(Bp + k0 + 36);
        }

        #pragma unroll
        for (int ks = 0; ks < 32; ks += 8) {
            uint32_t af[2][4], bf[4][2];
            #pragma unroll
            for (int i = 0; i < 2; i++) {
                const int m0 = wm * 32 + i * 16;
                uint2 lo = *(const uint2*)&As[m0 + gid][ks + 2 * tig];
                uint2 hi = *(const uint2*)&As[m0 + 8 + gid][ks + 2 * tig];
                af[i][0] = lo.x; af[i][1] = hi.x;
                af[i][2] = lo.y; af[i][3] = hi.y;
            }
            #pragma unroll
            for (int j = 0; j < 4; j++) {
                const int n0 = wn * 32 + j * 8;
                uint2 bb = *(const uint2*)&Bs[n0 + gid][ks + 2 * tig];
                bf[j][0] = bb.x; bf[j][1] = bb.y;
            }
            #pragma unroll
            for (int i = 0; i < 2; i++)
                #pragma unroll
                for (int j = 0; j < 4; j++)
                    mma_tf32(c[i][j], af[i], bf[j]);
        }
    }

    const float oml = 1.0f - lb;
    #pragma unroll
    for (int i = 0; i < 2; i++) {
        #pragma unroll
        for (int j = 0; j < 4; j++) {
            const int r0 = bm * 128 + wm * 32 + i * 16 + gid;
            const int cn = bn * 64 + wn * 32 + j * 8 + (tig << 1);
            float2 p0 = make_float2(c[i][j][0], c[i][j][1]);
            float2 p1 = make_float2(c[i][j][2], c[i][j][3]);
            if (vi) {
                float2 v0 = *(const float2*)(vi + r0 * DM + cn);
                float2 v1 = *(const float2*)(vi + (r0 + 8) * DM + cn);
                p0.x = oml * p0.x + lb * v0.x;
                p0.y = oml * p0.y + lb * v0.y;
                p1.x = oml * p1.x + lb * v1.x;
                p1.y = oml * p1.y + lb * v1.y;
            }
            *(float2*)(C + r0 * DM + cn) = p0;
            *(float2*)(C + (r0 + 8) * DM + cn) = p1;
        }
    }
}

__global__ __launch_bounds__(256, 2) void gemm_qkv(
    const float* __restrict__ x,
    const float* __restrict__ Wq, const float* __restrict__ Wk,
    const float* __restrict__ Wv,
    const float* __restrict__ vi, const float* __restrict__ lambp,
    float* __restrict__ q, float* __restrict__ k, float* __restrict__ v)
{
    const int z = blockIdx.z;
    const float* B = (z == 0) ? Wq : (z == 1) ? Wk : Wv;
    float* C = (z == 0) ? q : (z == 1) ? k : v;
    const float* mix = (z == 2) ? vi : nullptr;
    const float lb = (z == 2) ? *lambp : 0.0f;
    gemm_tf32_body(x, B, C, mix, lb, 0, DM);
}

__global__ __launch_bounds__(256, 2) void gemm_proj_splitk(
    const float* __restrict__ A, const float* __restrict__ B,
    float* __restrict__ p0, float* __restrict__ p1)
{
    const int z = blockIdx.z;
    gemm_tf32_body(A, B, z ? p1 : p0, nullptr, 0.0f,
                   z ? (DM / 2) : 0, z ? DM : (DM / 2));
}

__global__ __launch_bounds__(256) void add_kernel(
    const float* __restrict__ a, const float* __restrict__ b,
    float* __restrict__ c)
{
    const int i = (blockIdx.x * 256 + threadIdx.x) * 4;
    float4 x = *(const float4*)(a + i);
    float4 y = *(const float4*)(b + i);
    *(float4*)(c + i) = make_float4(x.x + y.x, x.y + y.y, x.z + y.z, x.w + y.w);
}

// ---------------------------------------------------------------------------
// Per-head RMSNorm + RoPE for q and k. grid = T, block = (32, 12).
// ---------------------------------------------------------------------------
__global__ void rmsrope_kernel()
{
    const int t = blockIdx.x;
    const int h = threadIdx.y;
    const int lane = threadIdx.x;

    const float inv = powf(10000.0f, -(float)lane * (1.0f / 32.0f));
    const float ang = (float)t * inv;
    float sn, cs;
    sincosf(ang, &sn, &cs);

    #pragma unroll
    for (int which = 0; which < 2; which++) {
        float* p = (which ? g_k : g_q) + t * DM + h * HD;
        float a = p[lane];
        float b = p[lane + 32];
        float ss = a * a + b * b;
        #pragma unroll
        for (int o = 16; o; o >>= 1)
            ss += __shfl_xor_sync(0xffffffffu, ss, o);
        const float r = rsqrtf(ss * (1.0f / 64.0f) + 1.1920929e-07f);
        a *= r; b *= r;
        p[lane]      =  a * cs + b * sn;
        p[lane + 32] =  b * cs - a * sn;
    }
}

// ---------------------------------------------------------------------------
// Causal flash attention, TF32 tensor cores — r12 body + split-KV pieces.
// grid = 480 (LPT-ordered items × heads), 256 threads = 8 warps.
// Each block computes a PARTIAL flash result over k-tiles [8p, 8p+8) and
// writes unnormalized acc + (m, l) per row; combine_kernel merges.
// ---------------------------------------------------------------------------
#define AP 68
#define SMEM_ATTN ((128 * AP + 64 * AP + 64 * AP + 128 * AP) * 4)

__global__ __launch_bounds__(256) void attn_kernel()
{
    extern __shared__ __align__(16) uint32_t smu[];
    uint32_t (*Qs)[AP] = (uint32_t(*)[AP])(smu);
    uint32_t (*Ks)[AP] = (uint32_t(*)[AP])(smu + 128 * AP);
    uint32_t (*Vs)[AP] = (uint32_t(*)[AP])(smu + 192 * AP);
    uint32_t (*Ps)[AP] = (uint32_t(*)[AP])(smu + 256 * AP);

    const int ord = blockIdx.x / NH;
    const int h   = blockIdx.x % NH;
    const int qb  = c_qb[ord];
    const int pc  = c_pc[ord];
    const int nkb = 2 * qb + 2;
    const int kb0 = 8 * pc;
    const int kbe = min(kb0 + 8, nkb);

    const int tid = threadIdx.x;
    const int wm = tid >> 5;
    const int lane = tid & 31;
    const int gid = lane >> 2, tig = lane & 3;
    const float scale = 0.125f;

    {
        const int lr = tid >> 1, lc = (tid & 1) << 5;
        const float* qp = g_q + (qb * 128 + lr) * DM + h * HD + lc;
        #pragma unroll
        for (int u = 0; u < 8; u++) {
            float4 v4 = *(const float4*)(qp + u * 4);
            Qs[lr][lc + u * 4 + 0] = f2tf(v4.x * scale);
            Qs[lr][lc + u * 4 + 1] = f2tf(v4.y * scale);
            Qs[lr][lc + u * 4 + 2] = f2tf(v4.z * scale);
            Qs[lr][lc + u * 4 + 3] = f2tf(v4.w * scale);
        }
    }

    float o[8][4] = {};
    float m0 = -1e30f, m1 = -1e30f, l0 = 0.0f, l1 = 0.0f;

    const int r0g = qb * 128 + wm * 16 + gid;

    for (int kb = kb0; kb < kbe; kb++) {
        {
            const int lr = tid >> 2, lc = (tid & 3) << 4;
            const float* kp = g_k + (kb * 64 + lr) * DM + h * HD + lc;
            const float* vp = g_v + (kb * 64 + lr) * DM + h * HD + lc;
            float4 kv[4], vv[4];
            #pragma unroll
            for (int u = 0; u < 4; u++) {
                kv[u] = *(const float4*)(kp + u * 4);
                vv[u] = *(const float4*)(vp + u * 4);
            }
            __syncthreads();
            #pragma unroll
            for (int u = 0; u < 4; u++) {
                Ks[lr][lc + u * 4 + 0] = f2tf(kv[u].x);
                Ks[lr][lc + u * 4 + 1] = f2tf(kv[u].y);
                Ks[lr][lc + u * 4 + 2] = f2tf(kv[u].z);
                Ks[lr][lc + u * 4 + 3] = f2tf(kv[u].w);
                Vs[lr][lc + u * 4 + 0] = f2tf(vv[u].x);
                Vs[lr][lc + u * 4 + 1] = f2tf(vv[u].y);
                Vs[lr][lc + u * 4 + 2] = f2tf(vv[u].z);
                Vs[lr][lc + u * 4 + 3] = f2tf(vv[u].w);
            }
            __syncthreads();
        }

        const bool act = (qb * 128 + wm * 16 + 15) >= kb * 64;
        if (act) {
            float s[8][4] = {};
            #pragma unroll
            for (int ks = 0; ks < 64; ks += 8) {
                uint32_t a[4];
                a[0] = Qs[wm * 16 + gid][ks + tig];
                a[1] = Qs[wm * 16 + 8 + gid][ks + tig];
                a[2] = Qs[wm * 16 + gid][ks + tig + 4];
                a[3] = Qs[wm * 16 + 8 + gid][ks + tig + 4];
                #pragma unroll
                for (int j = 0; j < 8; j++) {
                    uint32_t b[2];
                    b[0] = Ks[j * 8 + gid][ks + tig];
                    b[1] = Ks[j * 8 + gid][ks + tig + 4];
                    mma_tf32(s[j], a, b);
                }
            }

            if (kb >= 2 * qb) {
                #pragma unroll
                for (int j = 0; j < 8; j++) {
                    const int c0 = kb * 64 + j * 8 + (tig << 1);
                    if (c0 > r0g)         s[j][0] = -1e30f;
                    if (c0 + 1 > r0g)     s[j][1] = -1e30f;
                    if (c0 > r0g + 8)     s[j][2] = -1e30f;
                    if (c0 + 1 > r0g + 8) s[j][3] = -1e30f;
                }
            }

            float mx0 = -1e30f, mx1 = -1e30f;
            #pragma unroll
            for (int j = 0; j < 8; j++) {
                mx0 = fmaxf(mx0, fmaxf(s[j][0], s[j][1]));
                mx1 = fmaxf(mx1, fmaxf(s[j][2], s[j][3]));
            }
            #pragma unroll
            for (int off = 1; off <= 2; off <<= 1) {
                mx0 = fmaxf(mx0, __shfl_xor_sync(0xffffffffu, mx0, off));
                mx1 = fmaxf(mx1, __shfl_xor_sync(0xffffffffu, mx1, off));
            }
            const float nm0 = fmaxf(m0, mx0), nm1 = fmaxf(m1, mx1);
            const float al0 = __expf(m0 - nm0), al1 = __expf(m1 - nm1);
            float rs0 = 0.0f, rs1 = 0.0f;
            #pragma unroll
            for (int j = 0; j < 8; j++) {
                s[j][0] = __expf(s[j][0] - nm0);
                s[j][1] = __expf(s[j][1] - nm0);
                s[j][2] = __expf(s[j][2] - nm1);
                s[j][3] = __expf(s[j][3] - nm1);
                rs0 += s[j][0] + s[j][1];
                rs1 += s[j][2] + s[j][3];
            }
            #pragma unroll
            for (int off = 1; off <= 2; off <<= 1) {
                rs0 += __shfl_xor_sync(0xffffffffu, rs0, off);
                rs1 += __shfl_xor_sync(0xffffffffu, rs1, off);
            }
            l0 = l0 * al0 + rs0; m0 = nm0;
            l1 = l1 * al1 + rs1; m1 = nm1;
            #pragma unroll
            for (int j = 0; j < 8; j++) {
                o[j][0] *= al0; o[j][1] *= al0;
                o[j][2] *= al1; o[j][3] *= al1;
            }

            #pragma unroll
            for (int j = 0; j < 8; j++) {
                const int c = j * 8 + (tig << 1);
                uint2 p0 = make_uint2(f2tf(s[j][0]), f2tf(s[j][1]));
                uint2 p1 = make_uint2(f2tf(s[j][2]), f2tf(s[j][3]));
                *(uint2*)&Ps[wm * 16 + gid][c] = p0;
                *(uint2*)&Ps[wm * 16 + 8 + gid][c] = p1;
            }

            #pragma unroll
            for (int ks = 0; ks < 64; ks += 8) {
                uint32_t a[4];
                a[0] = Ps[wm * 16 + gid][ks + tig];
                a[1] = Ps[wm * 16 + 8 + gid][ks + tig];
                a[2] = Ps[wm * 16 + gid][ks + tig + 4];
                a[3] = Ps[wm * 16 + 8 + gid][ks + tig + 4];
                #pragma unroll
                for (int j = 0; j < 8; j++) {
                    uint32_t b[2];
                    b[0] = Vs[ks + tig][j * 8 + gid];
                    b[1] = Vs[ks + tig + 4][j * 8 + gid];
                    mma_tf32(o[j], a, b);
                }
            }
        }
    }

    // write PARTIAL: unnormalized acc + (m, l) per row
    float* pa = g_pacc + pc * (TT * DM);
    const int r = qb * 128 + wm * 16 + gid;
    #pragma unroll
    for (int j = 0; j < 8; j++) {
        const int c = h * HD + j * 8 + (tig << 1);
        *(float2*)(pa + r * DM + c) = make_float2(o[j][0], o[j][1]);
        *(float2*)(pa + (r + 8) * DM + c) = make_float2(o[j][2], o[j][3]);
    }
    if (tig == 0) {
        g_ml[(pc * NH + h) * TT + r]     = make_float2(m0, l0);
        g_ml[(pc * NH + h) * TT + r + 8] = make_float2(m1, l1);
    }
}

// ---------------------------------------------------------------------------
// Combine partial flash results. grid = TT, block = 192 (one float4 per thread)
// ---------------------------------------------------------------------------
__global__ __launch_bounds__(192) void combine_kernel()
{
    const int t = blockIdx.x;
    const int col = threadIdx.x * 4;
    const int qb = t >> 7;
    const int np = (qb >> 2) + 1;
    const int h = col >> 6;

    float m[4], l[4];
    #pragma unroll 4
    for (int p = 0; p < np; p++) {
        float2 ml = g_ml[(p * NH + h) * TT + t];
        m[p] = ml.x; l[p] = ml.y;
    }
    float M = m[0];
    #pragma unroll 4
    for (int p = 1; p < np; p++) M = fmaxf(M, m[p]);

    float den = 0.0f;
    float w[4];
    #pragma unroll 4
    for (int p = 0; p < np; p++) {
        w[p] = __expf(m[p] - M);
        den += l[p] * w[p];
    }
    const float inv = 1.0f / den;

    float4 acc = make_float4(0.f, 0.f, 0.f, 0.f);
    #pragma unroll 4
    for (int p = 0; p < np; p++) {
        float4 v = *(const float4*)(g_pacc + p * (TT * DM) + t * DM + col);
        acc.x += w[p] * v.x; acc.y += w[p] * v.y;
        acc.z += w[p] * v.z; acc.w += w[p] * v.w;
    }
    *(float4*)(g_o + t * DM + col) =
        make_float4(acc.x * inv, acc.y * inv, acc.z * inv, acc.w * inv);
}

// ---------------------------------------------------------------------------
extern "C" void kernel_launch(void* const* d_in, const int* in_sizes, int n_in,
                              void* d_out, int out_size)
{
    const float* x    = (const float*)d_in[0];
    const float* vi   = (const float*)d_in[1];
    const float* Wq   = (const float*)d_in[2];
    const float* Wk   = (const float*)d_in[3];
    const float* Wv   = (const float*)d_in[4];
    const float* Wp   = (const float*)d_in[5];
    const float* lamb = (const float*)d_in[6];
    float* out = (float*)d_out;

    float *q, *k, *v, *o;
    cudaGetSymbolAddress((void**)&q, g_q);
    cudaGetSymbolAddress((void**)&k, g_k);
    cudaGetSymbolAddress((void**)&v, g_v);
    cudaGetSymbolAddress((void**)&o, g_o);

    cudaFuncSetAttribute(attn_kernel,
                         cudaFuncAttributeMaxDynamicSharedMemorySize, SMEM_ATTN);

    gemm_qkv<<<dim3(DM / 64, TT / 128, 3), 256>>>(x, Wq, Wk, Wv, vi, lamb, q, k, v);
    rmsrope_kernel<<<TT, dim3(32, 12)>>>();
    attn_kernel<<<40 * NH, 256, SMEM_ATTN>>>();
    combine_kernel<<<TT, 192>>>();
    gemm_proj_splitk<<<dim3(DM / 64, TT / 128, 2), 256>>>(o, Wp, q, k);
    add_kernel<<<(TT * DM) / (256 * 4), 256>>>(q, k, out);
}